// round 4
// baseline (speedup 1.0000x reference)
#include <cuda_runtime.h>
#include <cstdint>

typedef unsigned long long u64;

__device__ float g_bufA[8388608];
__device__ float g_bufB[4194304];
__device__ float g_wT [21971520];   // transposed weights [c][ij][o]
__device__ float g_wTd[43943040];   // transposed+duplicated [c][ij][o dup x2]

__device__ __forceinline__ void cp_async16(uint32_t saddr, const float* gptr) {
    asm volatile("cp.async.cg.shared.global [%0], [%1], 16;" :: "r"(saddr), "l"(gptr));
}
#define CP_COMMIT() asm volatile("cp.async.commit_group;" ::: "memory")
#define CP_WAIT0()  asm volatile("cp.async.wait_group 0;" ::: "memory")
#define FFMA2(acc, w, v) asm("fma.rn.f32x2 %0, %1, %2, %0;" : "+l"(acc) : "l"(w), "l"(v))
#define MUL2(d, a, b)    asm("mul.rn.f32x2 %0, %1, %2;" : "=l"(d) : "l"(a), "l"(b))
#define PACK2(d, a, b)   asm("mov.b64 %0, {%1, %2};" : "=l"(d) : "f"(a), "f"(b))
#define UNPACK2(lo, hi, p) asm("mov.b64 {%0, %1}, %2;" : "=f"(lo), "=f"(hi) : "l"(p))

// Weight transpose: wt[(c*9+ij)*Co+o] = w[o][c][ij]; wtd duplicates each value 2x.
__global__ void transpose_w_kernel(const float* __restrict__ w, float* __restrict__ wt,
                                   float* __restrict__ wtd, int Ci, int Co)
{
    int i = blockIdx.x * 256 + threadIdx.x;
    int n = Ci * 9 * Co;
    if (i >= n) return;
    int o = i % Co;
    int cij = i / Co;
    int c = cij / 9, ij = cij % 9;
    float v = w[((size_t)o * Ci + c) * 9 + ij];
    wt[i] = v;
    wtd[2 * i] = v; wtd[2 * i + 1] = v;
}

// ───────── V1: stride-1, output tile 32x16, 2 px/thread, 8 outs, pixel-pair f32x2 ─────────
template<int CB>
__global__ void __launch_bounds__(256, 3) conv_s1_v1(
    const float* __restrict__ in, const float* __restrict__ wtd,
    const float* __restrict__ bias, const float* __restrict__ kern,
    float* __restrict__ out, int Ci, int Co, int H, int W, int tilesX)
{
    constexpr int ROWS = 18, PITCH = 40, CSZ = ROWS * PITCH;
    __shared__ __align__(16) float s_in[2][CB * CSZ];
    __shared__ __align__(16) float s_w[2][CB * 144];   // [c][ij][16 dup]

    const int tid = threadIdx.x;
    const int tx = tid % 16, ty = tid / 16;
    const int tX = blockIdx.x % tilesX, tY = blockIdx.x / tilesX;
    const int ocg = blockIdx.y, b = blockIdx.z;
    const int oh = tY * 16 + ty, ow0 = tX * 32 + 2 * tx;
    const size_t HW = (size_t)H * W;

    u64 kpair[9];
    if (kern) {
        const float* kp = kern + (size_t)b * 9 * HW + (size_t)oh * W + ow0;
        #pragma unroll
        for (int t = 0; t < 9; t++) {
            float2 kk = *(const float2*)(kp + (size_t)t * HW);
            PACK2(kpair[t], kk.x, kk.y);
        }
    } else {
        #pragma unroll
        for (int t = 0; t < 9; t++) PACK2(kpair[t], 1.0f, 1.0f);
    }

    u64 acc[8];
    #pragma unroll
    for (int u = 0; u < 8; u++) acc[u] = 0ull;

    for (int i = tid; i < 2 * CB * CSZ; i += 256) (&s_in[0][0])[i] = 0.0f;
    __syncthreads();

    const uint32_t sinA[2] = {(uint32_t)__cvta_generic_to_shared(&s_in[0][0]),
                              (uint32_t)__cvta_generic_to_shared(&s_in[1][0])};
    const uint32_t swA[2]  = {(uint32_t)__cvta_generic_to_shared(&s_w[0][0]),
                              (uint32_t)__cvta_generic_to_shared(&s_w[1][0])};
    const int NG = Ci / CB;

    auto stage = [&](int cg, int buf) {
        const int cbase = cg * CB;
        const float* ib = in + ((size_t)b * Ci + cbase) * HW;
        const uint32_t sb = sinA[buf];
        for (int idx = tid; idx < CB * ROWS * 10; idx += 256) {
            int q = idx % 10, r = (idx / 10) % ROWS, c = idx / (10 * ROWS);
            int gr = tY * 16 - 1 + r, gc = tX * 32 - 4 + 4 * q;
            if ((unsigned)gr < (unsigned)H && gc >= 0 && gc + 4 <= W)
                cp_async16(sb + (c * CSZ + r * PITCH + 4 * q) * 4,
                           ib + (size_t)c * HW + (size_t)gr * W + gc);
        }
        const uint32_t wb = swA[buf];
        for (int idx = tid; idx < CB * 36; idx += 256) {
            int c = idx / 36, rem = idx % 36, ij = rem / 4, q = rem % 4;
            cp_async16(wb + (c * 144 + ij * 16 + q * 4) * 4,
                       wtd + ((size_t)(cbase + c) * 9 + ij) * 2 * Co + (size_t)ocg * 16 + q * 4);
        }
    };

    stage(0, 0);
    CP_COMMIT();

    for (int cg = 0; cg < NG; cg++) {
        CP_WAIT0();
        __syncthreads();
        if (cg + 1 < NG) { stage(cg + 1, (cg + 1) & 1); CP_COMMIT(); }
        const int buf = cg & 1;

        #pragma unroll
        for (int c = 0; c < CB; c++) {
            const float* sp = &s_in[buf][c * CSZ + ty * PITCH + 2 * tx + 2];
            const float* wp = &s_w[buf][c * 144];
            #pragma unroll
            for (int i = 0; i < 3; i++) {
                const float2* rp = (const float2*)(sp + i * PITCH);
                float2 L0 = rp[0], L1 = rp[1], L2 = rp[2];
                u64 P[3];
                PACK2(P[0], L0.y, L1.x);
                PACK2(P[1], L1.x, L1.y);
                PACK2(P[2], L1.y, L2.x);
                #pragma unroll
                for (int j = 0; j < 3; j++) {
                    u64 vp;
                    MUL2(vp, P[j], kpair[3 * i + j]);
                    const ulonglong2* wq = (const ulonglong2*)(wp + (3 * i + j) * 16);
                    ulonglong2 w0 = wq[0], w1 = wq[1], w2 = wq[2], w3 = wq[3];
                    FFMA2(acc[0], w0.x, vp); FFMA2(acc[1], w0.y, vp);
                    FFMA2(acc[2], w1.x, vp); FFMA2(acc[3], w1.y, vp);
                    FFMA2(acc[4], w2.x, vp); FFMA2(acc[5], w2.y, vp);
                    FFMA2(acc[6], w3.x, vp); FFMA2(acc[7], w3.y, vp);
                }
            }
        }
    }

    #pragma unroll
    for (int u = 0; u < 8; u++) {
        int o = ocg * 8 + u;
        float lo, hi;
        UNPACK2(lo, hi, acc[u]);
        float bv = bias[o];
        float v0 = lo + bv, v1 = hi + bv;
        v0 = v0 > 0.0f ? v0 : 0.0f;
        v1 = v1 > 0.0f ? v1 : 0.0f;
        float2 r2 = make_float2(v0, v1);
        *(float2*)&out[((size_t)(b * Co + o) * H + oh) * W + ow0] = r2;
    }
}

// ───────── V2: stride-1, 16x16 image, 1 px/thread, 16 outs (output-pair f32x2) ─────────
template<int CB>
__global__ void __launch_bounds__(256, 2) conv_s1_v2(
    const float* __restrict__ in, const float* __restrict__ wt,
    const float* __restrict__ bias, const float* __restrict__ kern,
    float* __restrict__ out, int Ci, int Co)
{
    constexpr int ROWS = 18, PITCH = 24, CSZ = ROWS * PITCH;
    __shared__ __align__(16) float s_in[2][CB * CSZ];
    __shared__ __align__(16) float s_w[2][CB * 144];   // [c][ij][16]

    const int tid = threadIdx.x;
    const int w = tid % 16, h = tid / 16;
    const int ocg = blockIdx.y, b = blockIdx.z;
    const size_t HW = 256;

    float kreg[9];
    {
        const float* kp = kern + (size_t)b * 9 * HW + (size_t)h * 16 + w;
        #pragma unroll
        for (int t = 0; t < 9; t++) kreg[t] = kp[(size_t)t * HW];
    }

    u64 acc[8];
    #pragma unroll
    for (int u = 0; u < 8; u++) acc[u] = 0ull;

    for (int i = tid; i < 2 * CB * CSZ; i += 256) (&s_in[0][0])[i] = 0.0f;
    __syncthreads();

    const uint32_t sinA[2] = {(uint32_t)__cvta_generic_to_shared(&s_in[0][0]),
                              (uint32_t)__cvta_generic_to_shared(&s_in[1][0])};
    const uint32_t swA[2]  = {(uint32_t)__cvta_generic_to_shared(&s_w[0][0]),
                              (uint32_t)__cvta_generic_to_shared(&s_w[1][0])};
    const int NG = Ci / CB;

    auto stage = [&](int cg, int buf) {
        const int cbase = cg * CB;
        const float* ib = in + ((size_t)b * Ci + cbase) * HW;
        const uint32_t sb = sinA[buf];
        for (int idx = tid; idx < CB * ROWS * 4; idx += 256) {
            int q = idx % 4, r = (idx / 4) % ROWS, c = idx / (4 * ROWS);
            int gr = r - 1;
            if ((unsigned)gr < 16u)
                cp_async16(sb + (c * CSZ + r * PITCH + 4 + 4 * q) * 4,
                           ib + (size_t)c * HW + (size_t)gr * 16 + 4 * q);
        }
        const uint32_t wb = swA[buf];
        for (int idx = tid; idx < CB * 36; idx += 256) {
            int c = idx / 36, rem = idx % 36, ij = rem / 4, q = rem % 4;
            cp_async16(wb + (c * 144 + ij * 16 + q * 4) * 4,
                       wt + ((size_t)(cbase + c) * 9 + ij) * Co + (size_t)ocg * 16 + q * 4);
        }
    };

    stage(0, 0);
    CP_COMMIT();

    for (int cg = 0; cg < NG; cg++) {
        CP_WAIT0();
        __syncthreads();
        if (cg + 1 < NG) { stage(cg + 1, (cg + 1) & 1); CP_COMMIT(); }
        const int buf = cg & 1;

        #pragma unroll
        for (int c = 0; c < CB; c++) {
            const float* sp = &s_in[buf][c * CSZ + h * PITCH + w + 3];
            const float* wp = &s_w[buf][c * 144];
            #pragma unroll
            for (int t = 0; t < 9; t++) {
                float v = sp[(t / 3) * PITCH + (t % 3)] * kreg[t];
                u64 vv;
                PACK2(vv, v, v);
                const ulonglong2* wq = (const ulonglong2*)(wp + t * 16);
                ulonglong2 w0 = wq[0], w1 = wq[1], w2 = wq[2], w3 = wq[3];
                FFMA2(acc[0], w0.x, vv); FFMA2(acc[1], w0.y, vv);
                FFMA2(acc[2], w1.x, vv); FFMA2(acc[3], w1.y, vv);
                FFMA2(acc[4], w2.x, vv); FFMA2(acc[5], w2.y, vv);
                FFMA2(acc[6], w3.x, vv); FFMA2(acc[7], w3.y, vv);
            }
        }
    }

    #pragma unroll
    for (int p = 0; p < 8; p++) {
        int o = ocg * 16 + 2 * p;
        float lo, hi;
        UNPACK2(lo, hi, acc[p]);
        float v0 = lo + bias[o], v1 = hi + bias[o + 1];
        v0 = v0 > 0.0f ? v0 : 0.0f;
        v1 = v1 > 0.0f ? v1 : 0.0f;
        out[((size_t)(b * Co + o)     * 16 + h) * 16 + w] = v0;
        out[((size_t)(b * Co + o + 1) * 16 + h) * 16 + w] = v1;
    }
}

// ───────── V3: stride-2, output tile 16x16, 1 px/thread, 8 outs (output-pair f32x2) ─────────
template<int CB>
__global__ void __launch_bounds__(256, 3) conv_s2_v3(
    const float* __restrict__ in, const float* __restrict__ wt,
    const float* __restrict__ bias, const float* __restrict__ kern,
    float* __restrict__ out, int Ci, int Co, int H, int W, int tilesX)
{
    constexpr int ROWS = 33, PITCH = 40, CSZ = ROWS * PITCH;
    __shared__ __align__(16) float s_in[2][CB * CSZ];
    __shared__ __align__(16) float s_w[2][CB * 72];   // [c][ij][8]

    const int tid = threadIdx.x;
    const int tx = tid % 16, ty = tid / 16;
    const int tX = blockIdx.x % tilesX, tY = blockIdx.x / tilesX;
    const int ocg = blockIdx.y, b = blockIdx.z;
    const int Hout = H / 2, Wout = W / 2;
    const int oh = tY * 16 + ty, ow = tX * 16 + tx;
    const size_t HW = (size_t)H * W;

    float kreg[9];
    if (kern) {
        const float* kp = kern + (size_t)b * 9 * HW + (size_t)(oh * 2) * W + ow * 2;
        #pragma unroll
        for (int t = 0; t < 9; t++) kreg[t] = kp[(size_t)t * HW];
    } else {
        #pragma unroll
        for (int t = 0; t < 9; t++) kreg[t] = 1.0f;
    }

    u64 acc[4];
    #pragma unroll
    for (int u = 0; u < 4; u++) acc[u] = 0ull;

    for (int i = tid; i < 2 * CB * CSZ; i += 256) (&s_in[0][0])[i] = 0.0f;
    __syncthreads();

    const uint32_t sinA[2] = {(uint32_t)__cvta_generic_to_shared(&s_in[0][0]),
                              (uint32_t)__cvta_generic_to_shared(&s_in[1][0])};
    const uint32_t swA[2]  = {(uint32_t)__cvta_generic_to_shared(&s_w[0][0]),
                              (uint32_t)__cvta_generic_to_shared(&s_w[1][0])};
    const int NG = Ci / CB;

    auto stage = [&](int cg, int buf) {
        const int cbase = cg * CB;
        const float* ib = in + ((size_t)b * Ci + cbase) * HW;
        const uint32_t sb = sinA[buf];
        for (int idx = tid; idx < CB * ROWS * 10; idx += 256) {
            int q = idx % 10, r = (idx / 10) % ROWS, c = idx / (10 * ROWS);
            int gr = tY * 32 - 1 + r, gc = tX * 32 - 4 + 4 * q;
            if ((unsigned)gr < (unsigned)H && gc >= 0 && gc + 4 <= W)
                cp_async16(sb + (c * CSZ + r * PITCH + 4 * q) * 4,
                           ib + (size_t)c * HW + (size_t)gr * W + gc);
        }
        const uint32_t wb = swA[buf];
        for (int idx = tid; idx < CB * 18; idx += 256) {
            int c = idx / 18, rem = idx % 18, ij = rem / 2, q = rem % 2;
            cp_async16(wb + (c * 72 + ij * 8 + q * 4) * 4,
                       wt + ((size_t)(cbase + c) * 9 + ij) * Co + (size_t)ocg * 8 + q * 4);
        }
    };

    stage(0, 0);
    CP_COMMIT();

    for (int cg = 0; cg < NG; cg++) {
        CP_WAIT0();
        __syncthreads();
        if (cg + 1 < NG) { stage(cg + 1, (cg + 1) & 1); CP_COMMIT(); }
        const int buf = cg & 1;

        #pragma unroll
        for (int c = 0; c < CB; c++) {
            const float* sp = &s_in[buf][c * CSZ + (2 * ty) * PITCH + 2 * tx + 3];
            const float* wp = &s_w[buf][c * 72];
            #pragma unroll
            for (int t = 0; t < 9; t++) {
                float v = sp[(t / 3) * PITCH + (t % 3)] * kreg[t];
                u64 vv;
                PACK2(vv, v, v);
                const ulonglong2* wq = (const ulonglong2*)(wp + t * 8);
                ulonglong2 w0 = wq[0], w1 = wq[1];
                FFMA2(acc[0], w0.x, vv); FFMA2(acc[1], w0.y, vv);
                FFMA2(acc[2], w1.x, vv); FFMA2(acc[3], w1.y, vv);
            }
        }
    }

    #pragma unroll
    for (int p = 0; p < 4; p++) {
        int o = ocg * 8 + 2 * p;
        float lo, hi;
        UNPACK2(lo, hi, acc[p]);
        float v0 = lo + bias[o], v1 = hi + bias[o + 1];
        v0 = v0 > 0.0f ? v0 : 0.0f;
        v1 = v1 > 0.0f ? v1 : 0.0f;
        out[((size_t)(b * Co + o)     * Hout + oh) * Wout + ow] = v0;
        out[((size_t)(b * Co + o + 1) * Hout + oh) * Wout + ow] = v1;
    }
}

__global__ void pac_gauss_kernel(const float* __restrict__ f, float* __restrict__ out,
                                 int C, int H, int W, float coeff2)
{
    const int b = blockIdx.z;
    const int idx = blockIdx.x * blockDim.x + threadIdx.x;
    if (idx >= H * W) return;
    const int h = idx / W, w = idx % W;

    float acc[9];
    #pragma unroll
    for (int t = 0; t < 9; t++) acc[t] = 0.0f;

    const float* fb = f + (size_t)b * C * H * W;
    for (int c = 0; c < C; c++) {
        const float* fc = fb + (size_t)c * H * W;
        float ctr = fc[idx];
        #pragma unroll
        for (int i = 0; i < 3; i++)
        #pragma unroll
        for (int j = 0; j < 3; j++) {
            int hh = h + i - 1, ww = w + j - 1;
            float nb = (hh >= 0 && hh < H && ww >= 0 && ww < W) ? fc[hh * W + ww] : 0.0f;
            float d = nb - ctr;
            acc[i * 3 + j] += d * d;
        }
    }

    float* ob = out + (size_t)b * 9 * H * W;
    #pragma unroll
    for (int t = 0; t < 9; t++)
        ob[(size_t)t * H * W + idx] = expf(-0.5f * coeff2 * acc[t]);
}

// ───────── host side ─────────

static void conv_s1(const float* in, const float* wtd, const float* b, const float* kern,
                    float* out, int Ci, int Co, int H, int W)
{
    int tilesX = W / 32;
    dim3 grid(tilesX * (H / 16), Co / 8, 2);
    if (Ci % 4 == 0)
        conv_s1_v1<4><<<grid, 256>>>(in, wtd, b, kern, out, Ci, Co, H, W, tilesX);
    else
        conv_s1_v1<1><<<grid, 256>>>(in, wtd, b, kern, out, Ci, Co, H, W, tilesX);
}

static void conv_16(const float* in, const float* wt, const float* b, const float* kern,
                    float* out, int Ci, int Co)
{
    dim3 grid(1, Co / 16, 2);
    conv_s1_v2<8><<<grid, 256>>>(in, wt, b, kern, out, Ci, Co);
}

static void conv_s2(const float* in, const float* wt, const float* b, const float* kern,
                    float* out, int Ci, int Co, int H, int W)
{
    int tilesX = W / 32;
    dim3 grid(tilesX * (H / 32), Co / 8, 2);
    conv_s2_v3<2><<<grid, 256>>>(in, wt, b, kern, out, Ci, Co, H, W, tilesX);
}

static void pac_layer(const float* f, float* out, int C, int H, int W, float coeff2)
{
    int hw = H * W;
    dim3 grid((hw + 255) / 256, 1, 2);
    pac_gauss_kernel<<<grid, 256>>>(f, out, C, H, W, coeff2);
}

extern "C" void kernel_launch(void* const* d_in, const int* in_sizes, int n_in,
                              void* d_out, int out_size)
{
    const float* x = (const float*)d_in[0];
    const float* W14[14];
    const float* B14[14];
    for (int i = 0; i < 14; i++) {
        W14[i] = (const float*)d_in[1 + 2 * i];
        B14[i] = (const float*)d_in[2 + 2 * i];
    }

    float* bufA; float* bufB; float* wT; float* wTd;
    cudaGetSymbolAddress((void**)&bufA, g_bufA);
    cudaGetSymbolAddress((void**)&bufB, g_bufB);
    cudaGetSymbolAddress((void**)&wT,  g_wT);
    cudaGetSymbolAddress((void**)&wTd, g_wTd);

    // Per-layer transposed-weight offsets
    static const int CiA[14] = {1,64,64, 64,128,128, 128,256,256, 256,512,512, 512,1024};
    static const int CoA[14] = {64,64,64, 128,128,128, 256,256,256, 512,512,512, 1024,1024};
    size_t off[15];
    off[0] = 0;
    for (int l = 0; l < 14; l++) off[l + 1] = off[l] + (size_t)CiA[l] * 9 * CoA[l];

    const float* wt[14]; const float* wtd[14];
    for (int l = 0; l < 14; l++) {
        int n = CiA[l] * 9 * CoA[l];
        transpose_w_kernel<<<(n + 255) / 256, 256>>>(W14[l], wT + off[l], wTd + 2 * off[l],
                                                     CiA[l], CoA[l]);
        wt[l]  = wT + off[l];
        wtd[l] = wTd + 2 * off[l];
    }

    float* out = (float*)d_out;
    float* h1 = out;
    float* h2 = h1 + 8388608;
    float* h3 = h2 + 4194304;
    float* h4 = h3 + 2097152;
    float* h5 = h4 + 1048576;
    float* k2 = h5 + 524288;
    float* k3 = k2 + 294912;
    float* k4 = k3 + 73728;
    float* k5 = k4 + 18432;

    const float KC2 = 1e-4f * 1e-4f;

    // Stage 1
    conv_s1(x,    wtd[0], B14[0], nullptr, bufA, 1,  64, 256, 256);
    conv_s1(bufA, wtd[1], B14[1], nullptr, h1,   64, 64, 256, 256);
    conv_s2(h1,   wt[2],  B14[2], nullptr, bufA, 64, 64, 256, 256);   // -> 2,64,128,128

    // Stage 2
    pac_layer(bufA, k2, 64, 128, 128, KC2);
    conv_s1(bufA, wtd[3], B14[3], k2, bufB, 64,  128, 128, 128);
    conv_s1(bufB, wtd[4], B14[4], k2, h2,   128, 128, 128, 128);
    conv_s2(h2,   wt[5],  B14[5], k2, bufA, 128, 128, 128, 128);      // -> 2,128,64,64

    // Stage 3
    pac_layer(bufA, k3, 128, 64, 64, KC2);
    conv_s1(bufA, wtd[6], B14[6], k3, bufB, 128, 256, 64, 64);
    conv_s1(bufB, wtd[7], B14[7], k3, h3,   256, 256, 64, 64);
    conv_s2(h3,   wt[8],  B14[8], k3, bufA, 256, 256, 64, 64);        // -> 2,256,32,32

    // Stage 4 (guidance h4*2 -> coeff^2 = 4)
    pac_layer(bufA, k4, 256, 32, 32, 4.0f);
    conv_s1(bufA, wtd[9],  B14[9],  k4, bufB, 256, 512, 32, 32);
    conv_s1(bufB, wtd[10], B14[10], k4, h4,   512, 512, 32, 32);
    conv_s2(h4,   wt[11],  B14[11], k4, bufA, 512, 512, 32, 32);      // -> 2,512,16,16

    // Stage 5
    pac_layer(bufA, k5, 512, 16, 16, KC2);
    conv_16(bufA, wt[12], B14[12], k5, bufB, 512,  1024);
    conv_16(bufB, wt[13], B14[13], k5, h5,   1024, 1024);
}

// round 5
// speedup vs baseline: 1.4957x; 1.4957x over previous
#include <cuda_runtime.h>
#include <cstdint>

typedef unsigned long long u64;

__device__ float g_bufA[8388608];
__device__ float g_bufB[4194304];
__device__ float g_wT [21971520];   // transposed weights [c][ij][o]

__device__ __forceinline__ void cp_async16(uint32_t saddr, const float* gptr) {
    asm volatile("cp.async.cg.shared.global [%0], [%1], 16;" :: "r"(saddr), "l"(gptr));
}
#define CP_COMMIT() asm volatile("cp.async.commit_group;" ::: "memory")
#define CP_WAIT0()  asm volatile("cp.async.wait_group 0;" ::: "memory")
#define FFMA2(acc, w, v) asm("fma.rn.f32x2 %0, %1, %2, %0;" : "+l"(acc) : "l"(w), "l"(v))
#define PACK2(d, a, b)   asm("mov.b64 %0, {%1, %2};" : "=l"(d) : "f"(a), "f"(b))
#define UNPACK2(lo, hi, p) asm("mov.b64 {%0, %1}, %2;" : "=f"(lo), "=f"(hi) : "l"(p))

// wt[(c*9+ij)*Co+o] = w[o][c][ij]
__global__ void transpose_w_kernel(const float* __restrict__ w, float* __restrict__ wt,
                                   int Ci, int Co)
{
    int i = blockIdx.x * 256 + threadIdx.x;
    int n = Ci * 9 * Co;
    if (i >= n) return;
    int o = i % Co;
    int cij = i / Co;
    int c = cij / 9, ij = cij % 9;
    wt[i] = w[((size_t)o * Ci + c) * 9 + ij];
}

// ───────── stride-1: 16x16 tile, 1 px/thread, 8 outputs (output-pair f32x2) ─────────
template<int CB>
__global__ void __launch_bounds__(256) conv_s1(
    const float* __restrict__ in, const float* __restrict__ wt,
    const float* __restrict__ bias, const float* __restrict__ kern,
    float* __restrict__ out, int Ci, int Co, int H, int W, int tilesX)
{
    constexpr int ROWS = 18, PITCH = 24, CSZ = ROWS * PITCH;
    __shared__ __align__(16) float s_in[2][CB * CSZ];
    __shared__ __align__(16) float s_w[2][CB * 72];   // [c][ij][8]

    const int tid = threadIdx.x;
    const int tx = tid % 16, ty = tid / 16;
    const int tX = blockIdx.x % tilesX, tY = blockIdx.x / tilesX;
    const int ocg = blockIdx.y, b = blockIdx.z;
    const int oh = tY * 16 + ty, ow = tX * 16 + tx;
    const size_t HW = (size_t)H * W;

    float kreg[9];
    if (kern) {
        const float* kp = kern + (size_t)b * 9 * HW + (size_t)oh * W + ow;
        #pragma unroll
        for (int t = 0; t < 9; t++) kreg[t] = kp[(size_t)t * HW];
    } else {
        #pragma unroll
        for (int t = 0; t < 9; t++) kreg[t] = 1.0f;
    }

    u64 acc[4];
    #pragma unroll
    for (int p = 0; p < 4; p++) acc[p] = 0ull;

    for (int i = tid; i < 2 * CB * CSZ; i += 256) (&s_in[0][0])[i] = 0.0f;
    __syncthreads();

    const uint32_t sinA[2] = {(uint32_t)__cvta_generic_to_shared(&s_in[0][0]),
                              (uint32_t)__cvta_generic_to_shared(&s_in[1][0])};
    const uint32_t swA[2]  = {(uint32_t)__cvta_generic_to_shared(&s_w[0][0]),
                              (uint32_t)__cvta_generic_to_shared(&s_w[1][0])};
    const int NG = Ci / CB;
    const int gr0 = tY * 16 - 1;
    const int gcbase = tX * 16 - 4;   // col_smem = gc - gcbase

    auto stage = [&](int cg, int buf) {
        const int cbase = cg * CB;
        const float* ib = in + ((size_t)b * Ci + cbase) * HW;
        const uint32_t sb = sinA[buf];
        for (int idx = tid; idx < CB * ROWS * 6; idx += 256) {
            int q = idx % 6, r = (idx / 6) % ROWS, c = idx / (6 * ROWS);
            int gr = gr0 + r, gc = gcbase + 4 * q;
            if ((unsigned)gr < (unsigned)H && gc >= 0 && gc + 4 <= W)
                cp_async16(sb + (c * CSZ + r * PITCH + 4 * q) * 4,
                           ib + (size_t)c * HW + (size_t)gr * W + gc);
        }
        const uint32_t wb = swA[buf];
        for (int idx = tid; idx < CB * 18; idx += 256) {
            int c = idx / 18, rem = idx % 18, ij = rem / 2, q = rem % 2;
            cp_async16(wb + (c * 72 + ij * 8 + 4 * q) * 4,
                       wt + ((size_t)(cbase + c) * 9 + ij) * Co + (size_t)ocg * 8 + 4 * q);
        }
    };

    stage(0, 0);
    CP_COMMIT();

    const int base_off = ty * PITCH + tx + 3;

    for (int cg = 0; cg < NG; cg++) {
        CP_WAIT0();
        __syncthreads();
        if (cg + 1 < NG) { stage(cg + 1, (cg + 1) & 1); CP_COMMIT(); }
        const int buf = cg & 1;

        #pragma unroll
        for (int c = 0; c < CB; c++) {
            const float* sp = &s_in[buf][c * CSZ + base_off];
            const ulonglong2* wp = reinterpret_cast<const ulonglong2*>(&s_w[buf][c * 72]);
            #pragma unroll
            for (int t = 0; t < 9; t++) {
                float v = sp[(t / 3) * PITCH + (t % 3)] * kreg[t];
                u64 vv;
                PACK2(vv, v, v);
                ulonglong2 wa = wp[2 * t];
                ulonglong2 wbv = wp[2 * t + 1];
                FFMA2(acc[0], wa.x,  vv); FFMA2(acc[1], wa.y,  vv);
                FFMA2(acc[2], wbv.x, vv); FFMA2(acc[3], wbv.y, vv);
            }
        }
    }

    #pragma unroll
    for (int p = 0; p < 4; p++) {
        int o = ocg * 8 + 2 * p;
        float lo, hi;
        UNPACK2(lo, hi, acc[p]);
        float v0 = lo + bias[o], v1 = hi + bias[o + 1];
        v0 = v0 > 0.0f ? v0 : 0.0f;
        v1 = v1 > 0.0f ? v1 : 0.0f;
        out[((size_t)(b * Co + o)     * H + oh) * W + ow] = v0;
        out[((size_t)(b * Co + o + 1) * H + oh) * W + ow] = v1;
    }
}

// ───────── stride-2: 16x16 output tile, 1 px/thread, 8 outputs ─────────
template<int CB>
__global__ void __launch_bounds__(256) conv_s2(
    const float* __restrict__ in, const float* __restrict__ wt,
    const float* __restrict__ bias, const float* __restrict__ kern,
    float* __restrict__ out, int Ci, int Co, int H, int W, int tilesX)
{
    constexpr int ROWS = 33, PITCH = 40, CSZ = ROWS * PITCH;
    __shared__ __align__(16) float s_in[2][CB * CSZ];
    __shared__ __align__(16) float s_w[2][CB * 72];

    const int tid = threadIdx.x;
    const int tx = tid % 16, ty = tid / 16;
    const int tX = blockIdx.x % tilesX, tY = blockIdx.x / tilesX;
    const int ocg = blockIdx.y, b = blockIdx.z;
    const int Hout = H / 2, Wout = W / 2;
    const int oh = tY * 16 + ty, ow = tX * 16 + tx;
    const size_t HW = (size_t)H * W;

    float kreg[9];
    if (kern) {
        const float* kp = kern + (size_t)b * 9 * HW + (size_t)(oh * 2) * W + ow * 2;
        #pragma unroll
        for (int t = 0; t < 9; t++) kreg[t] = kp[(size_t)t * HW];
    } else {
        #pragma unroll
        for (int t = 0; t < 9; t++) kreg[t] = 1.0f;
    }

    u64 acc[4];
    #pragma unroll
    for (int p = 0; p < 4; p++) acc[p] = 0ull;

    for (int i = tid; i < 2 * CB * CSZ; i += 256) (&s_in[0][0])[i] = 0.0f;
    __syncthreads();

    const uint32_t sinA[2] = {(uint32_t)__cvta_generic_to_shared(&s_in[0][0]),
                              (uint32_t)__cvta_generic_to_shared(&s_in[1][0])};
    const uint32_t swA[2]  = {(uint32_t)__cvta_generic_to_shared(&s_w[0][0]),
                              (uint32_t)__cvta_generic_to_shared(&s_w[1][0])};
    const int NG = Ci / CB;
    const int gr0 = tY * 32 - 1;
    const int gcbase = tX * 32 - 4;

    auto stage = [&](int cg, int buf) {
        const int cbase = cg * CB;
        const float* ib = in + ((size_t)b * Ci + cbase) * HW;
        const uint32_t sb = sinA[buf];
        for (int idx = tid; idx < CB * ROWS * 10; idx += 256) {
            int q = idx % 10, r = (idx / 10) % ROWS, c = idx / (10 * ROWS);
            int gr = gr0 + r, gc = gcbase + 4 * q;
            if ((unsigned)gr < (unsigned)H && gc >= 0 && gc + 4 <= W)
                cp_async16(sb + (c * CSZ + r * PITCH + 4 * q) * 4,
                           ib + (size_t)c * HW + (size_t)gr * W + gc);
        }
        const uint32_t wb = swA[buf];
        for (int idx = tid; idx < CB * 18; idx += 256) {
            int c = idx / 18, rem = idx % 18, ij = rem / 2, q = rem % 2;
            cp_async16(wb + (c * 72 + ij * 8 + 4 * q) * 4,
                       wt + ((size_t)(cbase + c) * 9 + ij) * Co + (size_t)ocg * 8 + 4 * q);
        }
    };

    stage(0, 0);
    CP_COMMIT();

    const int base_off = (2 * ty) * PITCH + 2 * tx + 3;

    for (int cg = 0; cg < NG; cg++) {
        CP_WAIT0();
        __syncthreads();
        if (cg + 1 < NG) { stage(cg + 1, (cg + 1) & 1); CP_COMMIT(); }
        const int buf = cg & 1;

        #pragma unroll
        for (int c = 0; c < CB; c++) {
            const float* sp = &s_in[buf][c * CSZ + base_off];
            const ulonglong2* wp = reinterpret_cast<const ulonglong2*>(&s_w[buf][c * 72]);
            #pragma unroll
            for (int t = 0; t < 9; t++) {
                float v = sp[(t / 3) * PITCH + (t % 3)] * kreg[t];
                u64 vv;
                PACK2(vv, v, v);
                ulonglong2 wa = wp[2 * t];
                ulonglong2 wbv = wp[2 * t + 1];
                FFMA2(acc[0], wa.x,  vv); FFMA2(acc[1], wa.y,  vv);
                FFMA2(acc[2], wbv.x, vv); FFMA2(acc[3], wbv.y, vv);
            }
        }
    }

    #pragma unroll
    for (int p = 0; p < 4; p++) {
        int o = ocg * 8 + 2 * p;
        float lo, hi;
        UNPACK2(lo, hi, acc[p]);
        float v0 = lo + bias[o], v1 = hi + bias[o + 1];
        v0 = v0 > 0.0f ? v0 : 0.0f;
        v1 = v1 > 0.0f ? v1 : 0.0f;
        out[((size_t)(b * Co + o)     * Hout + oh) * Wout + ow] = v0;
        out[((size_t)(b * Co + o + 1) * Hout + oh) * Wout + ow] = v1;
    }
}

__global__ void pac_gauss_kernel(const float* __restrict__ f, float* __restrict__ out,
                                 int C, int H, int W, float coeff2)
{
    const int b = blockIdx.z;
    const int idx = blockIdx.x * blockDim.x + threadIdx.x;
    if (idx >= H * W) return;
    const int h = idx / W, w = idx % W;

    float acc[9];
    #pragma unroll
    for (int t = 0; t < 9; t++) acc[t] = 0.0f;

    const float* fb = f + (size_t)b * C * H * W;
    for (int c = 0; c < C; c++) {
        const float* fc = fb + (size_t)c * H * W;
        float ctr = fc[idx];
        #pragma unroll
        for (int i = 0; i < 3; i++)
        #pragma unroll
        for (int j = 0; j < 3; j++) {
            int hh = h + i - 1, ww = w + j - 1;
            float nb = (hh >= 0 && hh < H && ww >= 0 && ww < W) ? fc[hh * W + ww] : 0.0f;
            float d = nb - ctr;
            acc[i * 3 + j] += d * d;
        }
    }

    float* ob = out + (size_t)b * 9 * H * W;
    #pragma unroll
    for (int t = 0; t < 9; t++)
        ob[(size_t)t * H * W + idx] = expf(-0.5f * coeff2 * acc[t]);
}

// ───────── host side ─────────

static void conv_s1_l(const float* in, const float* wt, const float* b, const float* kern,
                      float* out, int Ci, int Co, int H, int W)
{
    int tilesX = W / 16;
    dim3 grid(tilesX * (H / 16), Co / 8, 2);
    if (Ci % 8 == 0)
        conv_s1<8><<<grid, 256>>>(in, wt, b, kern, out, Ci, Co, H, W, tilesX);
    else
        conv_s1<1><<<grid, 256>>>(in, wt, b, kern, out, Ci, Co, H, W, tilesX);
}

static void conv_s2_l(const float* in, const float* wt, const float* b, const float* kern,
                      float* out, int Ci, int Co, int H, int W)
{
    int tilesX = W / 32;
    dim3 grid(tilesX * (H / 32), Co / 8, 2);
    conv_s2<2><<<grid, 256>>>(in, wt, b, kern, out, Ci, Co, H, W, tilesX);
}

static void pac_layer(const float* f, float* out, int C, int H, int W, float coeff2)
{
    int hw = H * W;
    dim3 grid((hw + 255) / 256, 1, 2);
    pac_gauss_kernel<<<grid, 256>>>(f, out, C, H, W, coeff2);
}

extern "C" void kernel_launch(void* const* d_in, const int* in_sizes, int n_in,
                              void* d_out, int out_size)
{
    const float* x = (const float*)d_in[0];
    const float* W14[14];
    const float* B14[14];
    for (int i = 0; i < 14; i++) {
        W14[i] = (const float*)d_in[1 + 2 * i];
        B14[i] = (const float*)d_in[2 + 2 * i];
    }

    float* bufA; float* bufB; float* wT;
    cudaGetSymbolAddress((void**)&bufA, g_bufA);
    cudaGetSymbolAddress((void**)&bufB, g_bufB);
    cudaGetSymbolAddress((void**)&wT,  g_wT);

    static const int CiA[14] = {1,64,64, 64,128,128, 128,256,256, 256,512,512, 512,1024};
    static const int CoA[14] = {64,64,64, 128,128,128, 256,256,256, 512,512,512, 1024,1024};
    size_t off[15];
    off[0] = 0;
    for (int l = 0; l < 14; l++) off[l + 1] = off[l] + (size_t)CiA[l] * 9 * CoA[l];

    const float* wt[14];
    for (int l = 0; l < 14; l++) {
        int n = CiA[l] * 9 * CoA[l];
        transpose_w_kernel<<<(n + 255) / 256, 256>>>(W14[l], wT + off[l], CiA[l], CoA[l]);
        wt[l] = wT + off[l];
    }

    float* out = (float*)d_out;
    float* h1 = out;
    float* h2 = h1 + 8388608;
    float* h3 = h2 + 4194304;
    float* h4 = h3 + 2097152;
    float* h5 = h4 + 1048576;
    float* k2 = h5 + 524288;
    float* k3 = k2 + 294912;
    float* k4 = k3 + 73728;
    float* k5 = k4 + 18432;

    const float KC2 = 1e-4f * 1e-4f;

    // Stage 1
    conv_s1_l(x,    wt[0], B14[0], nullptr, bufA, 1,  64, 256, 256);
    conv_s1_l(bufA, wt[1], B14[1], nullptr, h1,   64, 64, 256, 256);
    conv_s2_l(h1,   wt[2], B14[2], nullptr, bufA, 64, 64, 256, 256);   // -> 2,64,128,128

    // Stage 2
    pac_layer(bufA, k2, 64, 128, 128, KC2);
    conv_s1_l(bufA, wt[3], B14[3], k2, bufB, 64,  128, 128, 128);
    conv_s1_l(bufB, wt[4], B14[4], k2, h2,   128, 128, 128, 128);
    conv_s2_l(h2,   wt[5], B14[5], k2, bufA, 128, 128, 128, 128);      // -> 2,128,64,64

    // Stage 3
    pac_layer(bufA, k3, 128, 64, 64, KC2);
    conv_s1_l(bufA, wt[6], B14[6], k3, bufB, 128, 256, 64, 64);
    conv_s1_l(bufB, wt[7], B14[7], k3, h3,   256, 256, 64, 64);
    conv_s2_l(h3,   wt[8], B14[8], k3, bufA, 256, 256, 64, 64);        // -> 2,256,32,32

    // Stage 4 (guidance h4*2 -> coeff^2 = 4)
    pac_layer(bufA, k4, 256, 32, 32, 4.0f);
    conv_s1_l(bufA, wt[9],  B14[9],  k4, bufB, 256, 512, 32, 32);
    conv_s1_l(bufB, wt[10], B14[10], k4, h4,   512, 512, 32, 32);
    conv_s2_l(h4,   wt[11], B14[11], k4, bufA, 512, 512, 32, 32);      // -> 2,512,16,16

    // Stage 5
    pac_layer(bufA, k5, 512, 16, 16, KC2);
    conv_s1_l(bufA, wt[12], B14[12], k5, bufB, 512,  1024, 16, 16);
    conv_s1_l(bufB, wt[13], B14[13], k5, h5,   1024, 1024, 16, 16);
}